// round 12
// baseline (speedup 1.0000x reference)
#include <cuda_runtime.h>

#define NN 100000
#define EE 3200000
#define ET (EE + NN)

// ---------------- scratch (device globals; no runtime allocation) ----------
__device__ int g_is64;
__device__ __align__(16) int2   g_edge[ET];        // decoded (src,dst) incl self-loops
__device__ __align__(16) float  g_h1[NN * 32];     // layer1 transformed features
__device__ __align__(8)  float2 g_a1s[NN];         // (a_src h0, a_src h1)
__device__ __align__(8)  float2 g_a1d[NN];         // (a_dst h0, a_dst h1)
__device__ __align__(8)  float2 g_s1[NN];          // segment expsum per head
__device__ __align__(16) float  g_out1[NN * 32];   // layer1 aggregate (unnormalized)
__device__ __align__(16) float  g_h2[NN * 40];
__device__ float g_a2s[NN];
__device__ float g_a2d[NN];
__device__ float g_s2[NN];

// ---------------- helpers ---------------------------------------------------
__device__ __forceinline__ void red_add_v4(float4* addr, float4 v) {
    asm volatile("red.global.add.v4.f32 [%0], {%1, %2, %3, %4};"
                 :: "l"(addr), "f"(v.x), "f"(v.y), "f"(v.z), "f"(v.w)
                 : "memory");
}
__device__ __forceinline__ void red_add_v2(float2* addr, float2 v) {
    asm volatile("red.global.add.v2.f32 [%0], {%1, %2};"
                 :: "l"(addr), "f"(v.x), "f"(v.y)
                 : "memory");
}
__device__ __forceinline__ float lrelu(float e) { return e > 0.f ? e : 0.2f * e; }

// ---------------- kernels ---------------------------------------------------

// h1 = X @ W1 (128->32). 64 nodes/block, 128 threads, thread = 4 nodes x 4 cols
// (cols c, c+8, c+16, c+24). 8 LDS.128 per 64 FMA. Dynamic smem 49664 B.
// Also: block 0 probes edge dtype; every block zeroes out1/s1 for its nodes.
__global__ void k_gemm1(const float* __restrict__ X, const float* __restrict__ W1,
                        const float* __restrict__ as1, const float* __restrict__ ad1,
                        const void* edges) {
    extern __shared__ float smem[];
    float (*Wt)[132] = (float(*)[132])smem;            // [col][k], +4 pad
    float4* Xs4 = (float4*)(smem + 32 * 132);          // [node][k4] 64x32
    int t = threadIdx.x;
    int node0 = blockIdx.x * 64;

    if (blockIdx.x == 0 && t == 0) {
        const long long* p = (const long long*)edges;
        int ok = 1;
        for (int i = 0; i < 64; i++) {
            long long v = p[i];
            if (v < 0 || v >= NN) { ok = 0; break; }
        }
        g_is64 = ok;
    }

    for (int i = t; i < 4096; i += 128) {
        int k = i >> 5, c = i & 31;
        Wt[c][k] = W1[i];
    }
    {
        const float4* Xg = (const float4*)X;
        for (int i = t; i < 2048; i += 128) {           // 64 rows x 32 f4
            int gi = node0 * 32 + i;
            Xs4[i] = (gi < NN * 32) ? Xg[gi] : make_float4(0.f, 0.f, 0.f, 0.f);
        }
    }
    {   // zero out1 rows (64 x 8 f4) and s1 for this block's nodes
        float4* o4 = (float4*)g_out1;
        for (int i = t; i < 512; i += 128) {
            int gi = node0 * 8 + i;
            if (gi < NN * 8) o4[gi] = make_float4(0.f, 0.f, 0.f, 0.f);
        }
        if (t < 64 && node0 + t < NN) g_s1[node0 + t] = make_float2(0.f, 0.f);
    }
    __syncthreads();

    int c = t & 7, g = t >> 3;                          // col base, node-group (4 nodes)
    const float4* wA = (const float4*)&Wt[c][0];
    const float4* wB = (const float4*)&Wt[c + 8][0];
    const float4* wC = (const float4*)&Wt[c + 16][0];
    const float4* wD = (const float4*)&Wt[c + 24][0];
    const float4* xr[4];
#pragma unroll
    for (int j = 0; j < 4; j++) xr[j] = Xs4 + (g * 4 + j) * 32;

    float aA[4] = {0.f, 0.f, 0.f, 0.f};
    float aB[4] = {0.f, 0.f, 0.f, 0.f};
    float aC[4] = {0.f, 0.f, 0.f, 0.f};
    float aD[4] = {0.f, 0.f, 0.f, 0.f};
#pragma unroll 2
    for (int kk = 0; kk < 32; kk++) {
        float4 wa = wA[kk], wb = wB[kk], wc = wC[kk], wd = wD[kk];
#pragma unroll
        for (int j = 0; j < 4; j++) {
            float4 x = xr[j][kk];
            aA[j] = fmaf(x.x, wa.x, fmaf(x.y, wa.y, fmaf(x.z, wa.z, fmaf(x.w, wa.w, aA[j]))));
            aB[j] = fmaf(x.x, wb.x, fmaf(x.y, wb.y, fmaf(x.z, wb.z, fmaf(x.w, wb.w, aB[j]))));
            aC[j] = fmaf(x.x, wc.x, fmaf(x.y, wc.y, fmaf(x.z, wc.z, fmaf(x.w, wc.w, aC[j]))));
            aD[j] = fmaf(x.x, wd.x, fmaf(x.y, wd.y, fmaf(x.z, wd.z, fmaf(x.w, wd.w, aD[j]))));
        }
    }

    // attention dot products: head0 = cols {c, c+8}, head1 = cols {c+16, c+24}
    float asA = as1[c], asB = as1[c + 8], asC = as1[c + 16], asD = as1[c + 24];
    float adA = ad1[c], adB = ad1[c + 8], adC = ad1[c + 16], adD = ad1[c + 24];
#pragma unroll
    for (int j = 0; j < 4; j++) {
        int node = node0 + g * 4 + j;
        if (node < NN) {
            float* hb = g_h1 + node * 32 + c;
            hb[0] = aA[j]; hb[8] = aB[j]; hb[16] = aC[j]; hb[24] = aD[j];
        }
        float vs0 = aA[j] * asA + aB[j] * asB;
        float vs1 = aC[j] * asC + aD[j] * asD;
        float vd0 = aA[j] * adA + aB[j] * adB;
        float vd1 = aC[j] * adC + aD[j] * adD;
#pragma unroll
        for (int off = 4; off; off >>= 1) {             // 8-lane group reduction
            vs0 += __shfl_xor_sync(0xffffffffu, vs0, off);
            vs1 += __shfl_xor_sync(0xffffffffu, vs1, off);
            vd0 += __shfl_xor_sync(0xffffffffu, vd0, off);
            vd1 += __shfl_xor_sync(0xffffffffu, vd1, off);
        }
        if (c == 0 && node < NN) {
            g_a1s[node] = make_float2(vs0, vs1);
            g_a1d[node] = make_float2(vd0, vd1);
        }
    }
}

// ---- layer1: warp-cooperative fused edge pass. 8 lanes per 2 edges. ----
__global__ void k_msg1(const void* edges) {
    int gidx = blockIdx.x * blockDim.x + threadIdx.x;
    int grp = gidx >> 3, q = gidx & 7;
    int i0 = grp * 2;
    if (i0 >= ET) return;
    int s0, d0, s1, d1;
    if (i0 < EE) {     // EE even, i0 even -> pair never straddles boundary
        if (g_is64) {
            const longlong2* ps = (const longlong2*)edges;
            const longlong2* pd = (const longlong2*)((const long long*)edges + EE);
            longlong2 a = __ldg(ps + (i0 >> 1));
            longlong2 b = __ldg(pd + (i0 >> 1));
            s0 = (int)a.x; s1 = (int)a.y; d0 = (int)b.x; d1 = (int)b.y;
        } else {
            const int2* ps = (const int2*)edges;
            const int2* pd = (const int2*)((const int*)edges + EE);
            int2 a = __ldg(ps + (i0 >> 1));
            int2 b = __ldg(pd + (i0 >> 1));
            s0 = a.x; s1 = a.y; d0 = b.x; d1 = b.y;
        }
    } else {
        s0 = d0 = i0 - EE; s1 = d1 = i0 + 1 - EE;
    }
    if (q == 0) *((int4*)(g_edge + i0)) = make_int4(s0, d0, s1, d1);

    float2 as0 = __ldg(&g_a1s[s0]);
    float2 ad0 = __ldg(&g_a1d[d0]);
    float2 as1v = __ldg(&g_a1s[s1]);
    float2 ad1v = __ldg(&g_a1d[d1]);
    float e00 = __expf(lrelu(as0.x + ad0.x));
    float e01 = __expf(lrelu(as0.y + ad0.y));
    float e10 = __expf(lrelu(as1v.x + ad1v.x));
    float e11 = __expf(lrelu(as1v.y + ad1v.y));
    if (q == 0) {
        red_add_v2(&g_s1[d0], make_float2(e00, e01));
        red_add_v2(&g_s1[d1], make_float2(e10, e11));
    }

    float4 v0 = __ldg((const float4*)(g_h1 + s0 * 32) + q);
    float4 v1 = __ldg((const float4*)(g_h1 + s1 * 32) + q);
    float a0 = (q < 4) ? e00 : e01;
    float a1 = (q < 4) ? e10 : e11;
    v0.x *= a0; v0.y *= a0; v0.z *= a0; v0.w *= a0;
    v1.x *= a1; v1.y *= a1; v1.z *= a1; v1.w *= a1;
    red_add_v4((float4*)(g_out1 + d0 * 32) + q, v0);
    red_add_v4((float4*)(g_out1 + d1 * 32) + q, v1);
}

// h2 = relu(out1/s1 + b1) @ W2 (32->40), fused normalization. 8 nodes / 320 thr.
// Also zeroes out + s2 for its nodes (consumed later by msg2).
__global__ void k_gemm2(const float* __restrict__ W2, const float* __restrict__ b1,
                        float* __restrict__ out) {
    __shared__ float Ws[32 * 40];
    __shared__ float Xs[8][32];
    int t = threadIdx.x;
    int node0 = blockIdx.x * 8;
    {   // zero out rows (8 x 10 f4) and s2
        float4* o4 = (float4*)out;
        for (int i = t; i < 80; i += 320) {
            int gi = node0 * 10 + i;
            if (gi < NN * 10) o4[gi] = make_float4(0.f, 0.f, 0.f, 0.f);
        }
        if (t < 8 && node0 + t < NN) g_s2[node0 + t] = 0.f;
    }
    for (int i = t; i < 32 * 40; i += 320) Ws[i] = W2[i];
    for (int i = t; i < 8 * 32; i += 320) {
        int r = i >> 5, c = i & 31;
        float2 s = g_s1[node0 + r];
        float sv = (c < 16) ? s.x : s.y;
        float v = g_out1[(node0 + r) * 32 + c] / (sv + 1e-16f) + b1[c];
        Xs[r][c] = v > 0.f ? v : 0.f;
    }
    __syncthreads();
    int local = t / 40, col = t % 40;
    int node = node0 + local;
    if (node >= NN) return;
    float sum = 0.f;
#pragma unroll
    for (int k = 0; k < 32; k++) sum = fmaf(Xs[local][k], Ws[k * 40 + col], sum);
    g_h2[node * 40 + col] = sum;
}

// a_src2/a_dst2: one warp per node over 40 channels.
__global__ void k_a2(const float* __restrict__ as2, const float* __restrict__ ad2) {
    int node = blockIdx.x * 8 + (threadIdx.x >> 5);
    int lane = threadIdx.x & 31;
    if (node >= NN) return;
    const float* row = g_h2 + node * 40;
    float v1 = row[lane];
    float v2 = (lane < 8) ? row[32 + lane] : 0.f;
    float sv = v1 * as2[lane] + ((lane < 8) ? v2 * as2[32 + lane] : 0.f);
    float dv = v1 * ad2[lane] + ((lane < 8) ? v2 * ad2[32 + lane] : 0.f);
#pragma unroll
    for (int off = 16; off; off >>= 1) {
        sv += __shfl_xor_sync(0xffffffffu, sv, off);
        dv += __shfl_xor_sync(0xffffffffu, dv, off);
    }
    if (lane == 0) { g_a2s[node] = sv; g_a2d[node] = dv; }
}

// ---- layer2: warp-cooperative fused edge pass into d_out. 8 lanes per 2 edges. ----
__global__ void k_msg2(float* __restrict__ out) {
    int gidx = blockIdx.x * blockDim.x + threadIdx.x;
    int grp = gidx >> 3, q = gidx & 7;
    int i0 = grp * 2;
    if (i0 >= ET) return;
    int4 e4 = __ldg((const int4*)(g_edge + i0));
    int s0 = e4.x, d0 = e4.y, s1 = e4.z, d1 = e4.w;

    float ex0 = __expf(lrelu(__ldg(&g_a2s[s0]) + __ldg(&g_a2d[d0])));
    float ex1 = __expf(lrelu(__ldg(&g_a2s[s1]) + __ldg(&g_a2d[d1])));
    if (q == 0) {
        atomicAdd(&g_s2[d0], ex0);
        atomicAdd(&g_s2[d1], ex1);
    }

    const float4* hp0 = (const float4*)(g_h2 + s0 * 40);
    const float4* hp1 = (const float4*)(g_h2 + s1 * 40);
    float4* op0 = (float4*)(out + d0 * 40);
    float4* op1 = (float4*)(out + d1 * 40);
    float4 v0 = __ldg(hp0 + q);
    float4 v1 = __ldg(hp1 + q);
    v0.x *= ex0; v0.y *= ex0; v0.z *= ex0; v0.w *= ex0;
    v1.x *= ex1; v1.y *= ex1; v1.z *= ex1; v1.w *= ex1;
    red_add_v4(op0 + q, v0);
    red_add_v4(op1 + q, v1);
    if (q < 2) {
        float4 w0 = __ldg(hp0 + 8 + q);
        float4 w1 = __ldg(hp1 + 8 + q);
        w0.x *= ex0; w0.y *= ex0; w0.z *= ex0; w0.w *= ex0;
        w1.x *= ex1; w1.y *= ex1; w1.z *= ex1; w1.w *= ex1;
        red_add_v4(op0 + 8 + q, w0);
        red_add_v4(op1 + 8 + q, w1);
    }
}

// Final: normalize by s2 and add bias.
__global__ void k_fin(float* __restrict__ out, const float* __restrict__ b2) {
    int i = blockIdx.x * blockDim.x + threadIdx.x;
    if (i >= NN * 40) return;
    int n = i / 40, c = i - n * 40;
    out[i] = out[i] / (g_s2[n] + 1e-16f) + b2[c];
}

// ---------------- launch ----------------------------------------------------
extern "C" void kernel_launch(void* const* d_in, const int* in_sizes, int n_in,
                              void* d_out, int out_size) {
    const float* X   = (const float*)d_in[0];
    const void*  edges = d_in[1];
    const float* W1  = (const float*)d_in[3];
    const float* as1 = (const float*)d_in[4];
    const float* ad1 = (const float*)d_in[5];
    const float* b1  = (const float*)d_in[6];
    const float* W2  = (const float*)d_in[7];
    const float* as2 = (const float*)d_in[8];
    const float* ad2 = (const float*)d_in[9];
    const float* b2  = (const float*)d_in[10];
    float* out = (float*)d_out;

    const int GEMM1_SMEM = (32 * 132) * 4 + 64 * 128 * 4;   // 49664 B
    cudaFuncSetAttribute(k_gemm1, cudaFuncAttributeMaxDynamicSharedMemorySize, GEMM1_SMEM);

    const long long TH = (long long)(ET / 2) * 8;      // 8 lanes per 2 edges
    const int EGW = (int)((TH + 255) / 256);

    k_gemm1<<<(NN + 63) / 64, 128, GEMM1_SMEM>>>(X, W1, as1, ad1, edges);
    k_msg1<<<EGW, 256>>>(edges);
    k_gemm2<<<(NN + 7) / 8, 320>>>(W2, b1, out);
    k_a2<<<(NN + 7) / 8, 256>>>(as2, ad2);
    k_msg2<<<EGW, 256>>>(out);
    k_fin<<<(NN * 40 + 255) / 256, 256>>>(out, b2);
}